// round 8
// baseline (speedup 1.0000x reference)
#include <cuda_runtime.h>
#include <cuda_bf16.h>

// Output: [Cm1, 1, R, NC+4] fp32 flat.  rowlen = 85, NC = 81.
//
// Single write-once kernel, one float4 per thread per class plane:
//   k0 = (4t) mod 85
//   k0 <= 77 : pure cls copy  -> LDG.128 cls4[t - r] ; STG.128      (~92%)
//   k0 >= 78 : float4 overlaps the 4 box slots of row r -> compute  (~8%)
// Box values (row r): x,y,w,h = rois[r]; tx..th = regr[r, c, 0..3]
//   gx=rint(w*tx+x) gy=rint(h*ty+y) gw=rint(w*exp(tw)) gh=rint(h*exp(th))
//   box = {gx/W, gy/H, (gx+gw)/W, (gy+gh)/H}

__global__ void __launch_bounds__(256)
bb_fused_kernel(const float* __restrict__ cls,     // [R, NC]
                const float4* __restrict__ cls4,   // same, as float4
                const float4* __restrict__ regr4,  // [R, Cm1] of float4
                const float4* __restrict__ rois,   // [R] of float4
                float4* __restrict__ out4,
                int perC4,       // 85*R/4 float4s per class plane
                int R, int Cm1, int NC,
                float invW, float invH)
{
    int t = blockIdx.x * 256 + threadIdx.x;
    if (t >= perC4) return;
    const int c = blockIdx.y;

    const int rowlen = NC + 4;                       // 85
    unsigned rem0 = (unsigned)t << 2;
    unsigned r  = rem0 / (unsigned)rowlen;           // const-divisor -> umulhi
    unsigned k0 = rem0 - r * (unsigned)rowlen;

    float4* dst = out4 + (size_t)c * (size_t)perC4 + (size_t)t;

    if (k0 <= (unsigned)(NC - 4)) {
        // Pure class copy: elements 81r + k0 .. +3, aligned float4 in cls.
        float4 v = __ldg(&cls4[t - (int)r]);
        __stcs(dst, v);
        return;
    }

    // Slow path: this float4 contains box element(s) of row r
    // (and possibly leading cls of row r, trailing cls of row r+1).
    float4 roi = __ldg(&rois[r]);                    // x, y, w, h
    float4 tg  = __ldg(&regr4[(size_t)r * Cm1 + c]); // tx, ty, tw, th

    float gx = rintf(fmaf(roi.z, tg.x, roi.x));
    float gy = rintf(fmaf(roi.w, tg.y, roi.y));
    float gw = rintf(roi.z * expf(tg.z));
    float gh = rintf(roi.w * expf(tg.w));

    float b[4];
    b[0] = gx * invW;
    b[1] = gy * invH;
    b[2] = (gx + gw) * invW;
    b[3] = (gy + gh) * invH;

    float v[4];
#pragma unroll
    for (int i = 0; i < 4; ++i) {
        int k = (int)k0 + i;
        int rr = (int)r;
        if (k >= rowlen) { k -= rowlen; ++rr; }      // wrap: rr < R guaranteed
        if (k < NC)      v[i] = __ldg(&cls[(size_t)rr * NC + k]);
        else             v[i] = b[k - NC];
    }
    float4 o; o.x = v[0]; o.y = v[1]; o.z = v[2]; o.w = v[3];
    __stcs(dst, o);
}

// ---------------- Generic scalar fallback (shape safety net) ----------------
__global__ void __launch_bounds__(256)
bb_generic_kernel(const float* __restrict__ regr,
                  const float* __restrict__ cls,
                  const float4* __restrict__ rois,
                  float* __restrict__ out,
                  int R, int Cm1, int NC,
                  float invW, float invH,
                  long long total)
{
    long long idx = (long long)blockIdx.x * blockDim.x + threadIdx.x;
    long long stride = (long long)gridDim.x * blockDim.x;
    const int rowlen = NC + 4;
    const long long perC = (long long)R * rowlen;
    for (; idx < total; idx += stride) {
        int c   = (int)(idx / perC);
        int rem = (int)(idx - (long long)c * perC);
        int r   = rem / rowlen;
        int k   = rem - r * rowlen;
        float val;
        if (k < NC) {
            val = cls[(long long)r * NC + k];
        } else {
            float4 roi = __ldg(&rois[r]);
            const float* rg = regr + ((long long)r * Cm1 + c) * 4;
            int comp = k - NC;
            if (comp == 0)      val = rintf(fmaf(roi.z, rg[0], roi.x)) * invW;
            else if (comp == 1) val = rintf(fmaf(roi.w, rg[1], roi.y)) * invH;
            else if (comp == 2) val = (rintf(fmaf(roi.z, rg[0], roi.x)) +
                                       rintf(roi.z * expf(rg[2]))) * invW;
            else                val = (rintf(fmaf(roi.w, rg[1], roi.y)) +
                                       rintf(roi.w * expf(rg[3]))) * invH;
        }
        out[idx] = val;
    }
}

extern "C" void kernel_launch(void* const* d_in, const int* in_sizes, int n_in,
                              void* d_out, int out_size)
{
    const float*  regr = (const float*)d_in[0];   // [1, R, 4*Cm1]
    const float*  cls  = (const float*)d_in[1];   // [1, R, NC]
    const float4* rois = (const float4*)d_in[2];  // [1, R, 4]

    const int R   = in_sizes[2] / 4;
    const int Cm1 = in_sizes[0] / (R * 4);
    const int NC  = in_sizes[1] / R;              // 81
    const int rowlen = NC + 4;

    // H = W = isqrt(b_elems / 3) (square image)
    long long hw = (long long)in_sizes[3] / 3;
    int side = 1;
    while ((long long)(side + 1) * (side + 1) <= hw) ++side;
    const float invW = 1.0f / (float)side;
    const float invH = 1.0f / (float)side;

    float* out = (float*)d_out;
    const long long perC  = (long long)R * rowlen;
    const long long total = (long long)out_size;

    const bool fast = (perC % 4 == 0) && (NC >= 4) &&
                      (total == (long long)Cm1 * perC);

    if (fast) {
        const int perC4 = (int)(perC >> 2);
        dim3 grid((perC4 + 255) / 256, Cm1);
        bb_fused_kernel<<<grid, 256>>>(
            cls, (const float4*)cls, (const float4*)regr, rois,
            (float4*)out, perC4, R, Cm1, NC, invW, invH);
    } else {
        long long blocks = (total + 255) / 256;
        if (blocks > 262144) blocks = 262144;
        bb_generic_kernel<<<(unsigned)blocks, 256>>>(
            regr, cls, rois, out, R, Cm1, NC, invW, invH, total);
    }
}

// round 9
// speedup vs baseline: 2.5260x; 2.5260x over previous
#include <cuda_runtime.h>
#include <cuda_bf16.h>

// Output: [Cm1, 1, R, NC+4] fp32 flat.  rowlen = 85, NC = 81.
//
// Two kernels, write-mostly-once:
//   A: branchless float4 broadcast of cls into the whole output
//      (box slots temporarily hold garbage cls bytes).   ~143us, HBM-bound
//   B: one lane per box element (c, r, j), quad-cooperative loads,
//      overwrites the 4 box slots of every row.           target ~30us

// ---------------- Kernel A: cls broadcast, 1 float4 per thread ----------------
__global__ void __launch_bounds__(256)
cls_broadcast_kernel(const float4* __restrict__ cls4,
                     float4* __restrict__ out4,
                     int perC4,          // rowlen*R/4 (float4s per class)
                     int rowlen,         // NC+4
                     int maxClsIdx)      // (NC*R - 4) / 4
{
    int t = blockIdx.x * 256 + threadIdx.x;
    if (t >= perC4) return;
    const int c = blockIdx.y;

    unsigned rem0 = (unsigned)t << 2;
    unsigned r  = rem0 / (unsigned)rowlen;             // const-div -> umulhi
    unsigned k0 = rem0 - r * (unsigned)rowlen;
    unsigned rr = r + (k0 >= (unsigned)(rowlen - 3));  // carry -> next row
    int idx = t - (int)rr;
    idx = min(idx, maxClsIdx);

    out4[(size_t)c * (size_t)perC4 + (size_t)t] = __ldg(&cls4[idx]);
}

// ---------------- Kernel B: box elements, 1 lane per element ----------------
// u = 4r + j  (j = component 0..3), c = blockIdx.y.
// Per quad of lanes: same rois[r] and regr4[r*Cm1+c] (hardware broadcast).
// Branchless component select; expf executes once per warp (SIMD over j>=2 data).
__global__ void __launch_bounds__(256)
box_kernel_v2(const float4* __restrict__ regr4,   // [R, Cm1] of float4
              const float4* __restrict__ rois,    // [R] of float4
              float* __restrict__ out,
              int R, int Cm1, int NC,
              float invW, float invH)
{
    int u = blockIdx.x * 256 + threadIdx.x;       // 0 .. 4R-1
    if (u >= 4 * R) return;
    const int c = blockIdx.y;
    const int r = u >> 2;
    const int j = u & 3;

    float4 roi = __ldg(&rois[r]);                      // x, y, w, h
    float4 tg  = __ldg(&regr4[(size_t)r * Cm1 + c]);   // tx, ty, tw, th

    const bool odd = (j & 1);          // y-type component
    const bool hi  = (j >= 2);         // needs the exp term

    float s   = odd ? roi.w : roi.z;   // h : w
    float o   = odd ? roi.y : roi.x;   // y : x
    float inv = odd ? invH  : invW;
    float t1  = odd ? tg.y  : tg.x;    // ty : tx
    float t2  = odd ? tg.w  : tg.z;    // th : tw

    float base  = rintf(fmaf(s, t1, o));               // gx or gy
    float extra = rintf(s * expf(t2));                 // gw or gh (whole warp)
    float val   = (base + (hi ? extra : 0.0f)) * inv;

    out[((size_t)c * R + r) * (size_t)(NC + 4) + NC + j] = val;
}

// ---------------- Generic scalar fallback (shape safety net) ----------------
__global__ void __launch_bounds__(256)
bb_generic_kernel(const float* __restrict__ regr,
                  const float* __restrict__ cls,
                  const float4* __restrict__ rois,
                  float* __restrict__ out,
                  int R, int Cm1, int NC,
                  float invW, float invH,
                  long long total)
{
    long long idx = (long long)blockIdx.x * blockDim.x + threadIdx.x;
    long long stride = (long long)gridDim.x * blockDim.x;
    const int rowlen = NC + 4;
    const long long perC = (long long)R * rowlen;
    for (; idx < total; idx += stride) {
        int c   = (int)(idx / perC);
        int rem = (int)(idx - (long long)c * perC);
        int r   = rem / rowlen;
        int k   = rem - r * rowlen;
        float val;
        if (k < NC) {
            val = cls[(long long)r * NC + k];
        } else {
            float4 roi = __ldg(&rois[r]);
            const float* rg = regr + ((long long)r * Cm1 + c) * 4;
            int comp = k - NC;
            if (comp == 0)      val = rintf(fmaf(roi.z, rg[0], roi.x)) * invW;
            else if (comp == 1) val = rintf(fmaf(roi.w, rg[1], roi.y)) * invH;
            else if (comp == 2) val = (rintf(fmaf(roi.z, rg[0], roi.x)) +
                                       rintf(roi.z * expf(rg[2]))) * invW;
            else                val = (rintf(fmaf(roi.w, rg[1], roi.y)) +
                                       rintf(roi.w * expf(rg[3]))) * invH;
        }
        out[idx] = val;
    }
}

extern "C" void kernel_launch(void* const* d_in, const int* in_sizes, int n_in,
                              void* d_out, int out_size)
{
    const float*  regr = (const float*)d_in[0];   // [1, R, 4*Cm1]
    const float*  cls  = (const float*)d_in[1];   // [1, R, NC]
    const float4* rois = (const float4*)d_in[2];  // [1, R, 4]

    const int R   = in_sizes[2] / 4;
    const int Cm1 = in_sizes[0] / (R * 4);
    const int NC  = in_sizes[1] / R;              // 81
    const int rowlen = NC + 4;

    // H = W = isqrt(b_elems / 3) (square image)
    long long hw = (long long)in_sizes[3] / 3;
    int side = 1;
    while ((long long)(side + 1) * (side + 1) <= hw) ++side;
    const float invW = 1.0f / (float)side;
    const float invH = 1.0f / (float)side;

    float* out = (float*)d_out;
    const long long perC  = (long long)R * rowlen;
    const long long total = (long long)out_size;

    const bool fast = (perC % 4 == 0) &&
                      (((long long)R * NC) % 4 == 0) &&
                      (total == (long long)Cm1 * perC);

    if (fast) {
        // A: broadcast cls into everything
        const int perC4 = (int)(perC >> 2);
        const int maxClsIdx = (int)(((long long)R * NC - 4) >> 2);
        dim3 gridA((perC4 + 255) / 256, Cm1);
        cls_broadcast_kernel<<<gridA, 256>>>(
            (const float4*)cls, (float4*)out, perC4, rowlen, maxClsIdx);

        // B: overwrite box slots, one lane per element
        dim3 gridB((4 * R + 255) / 256, Cm1);
        box_kernel_v2<<<gridB, 256>>>(
            (const float4*)regr, rois, out, R, Cm1, NC, invW, invH);
    } else {
        long long blocks = (total + 255) / 256;
        if (blocks > 262144) blocks = 262144;
        bb_generic_kernel<<<(unsigned)blocks, 256>>>(
            regr, cls, rois, out, R, Cm1, NC, invW, invH, total);
    }
}

// round 10
// speedup vs baseline: 3.4528x; 1.3669x over previous
#include <cuda_runtime.h>
#include <cuda_bf16.h>

// Output: [Cm1, 1, R, NC+4] fp32 flat. Specialized for rowlen = 85 (NC = 81).
//
// Single kernel, every output byte written exactly once.
// Structure: 4 rows = 340 elements = exactly 85 float4s per group.
// Boundary float4 positions within a group (touch box slots): {20,21,41,42,62,63,84}.
// gridDim.x = FASTB + SLOWB; blocks below FASTB do pure uniform copies over the
// remapped 78 fast positions, blocks above handle the 7 boundary positions with
// the box math + cls blend. gridDim.y = class c.

__global__ void __launch_bounds__(256)
bb_onepass_kernel(const float* __restrict__ cls,     // [R, 81]
                  const float4* __restrict__ cls4,
                  const float4* __restrict__ regr4,  // [R, Cm1] of float4
                  const float4* __restrict__ rois,   // [R] of float4
                  float4* __restrict__ out4,
                  int perC4,        // 85*R/4
                  int R, int Cm1,
                  int fastBlocks,   // covers 78*(R/4) threads
                  int fastCount,    // 78*(R/4)
                  int slowCount,    // 7*(R/4)
                  float invW, float invH)
{
    const int c = blockIdx.y;
    float4* plane = out4 + (size_t)c * (size_t)perC4;

    if (blockIdx.x < (unsigned)fastBlocks) {
        // ---------- FAST: pure cls copy, warps fully uniform ----------
        int tf = blockIdx.x * 256 + threadIdx.x;
        if (tf >= fastCount) return;
        unsigned w = (unsigned)tf % 78u;              // const-div
        unsigned g = (unsigned)tf / 78u;
        unsigned p = w + 2u * ((w >= 20u) + (w >= 39u) + (w >= 58u));
        int t = (int)(85u * g + p);                   // float4 index in plane
        unsigned r = ((unsigned)t << 2) / 85u;        // row (float4 never crosses)
        plane[t] = __ldg(&cls4[t - (int)r]);
        return;
    }

    // ---------- SLOW: boundary float4s (contain box elements) ----------
    int u = (blockIdx.x - fastBlocks) * 256 + threadIdx.x;
    if (u >= slowCount) return;
    unsigned q = (unsigned)u % 7u;
    unsigned g = (unsigned)u / 7u;
    unsigned p = (q == 6u) ? 84u : (20u + 21u * (q >> 1) + (q & 1u));
    int t = (int)(85u * g + p);

    unsigned rem0 = (unsigned)t << 2;
    unsigned r  = rem0 / 85u;
    unsigned k0 = rem0 - r * 85u;

    float4 roi = __ldg(&rois[r]);                      // x, y, w, h
    float4 tg  = __ldg(&regr4[(size_t)r * Cm1 + c]);   // tx, ty, tw, th

    float gx = rintf(fmaf(roi.z, tg.x, roi.x));
    float gy = rintf(fmaf(roi.w, tg.y, roi.y));
    float gw = rintf(roi.z * expf(tg.z));
    float gh = rintf(roi.w * expf(tg.w));

    float b[4];
    b[0] = gx * invW;
    b[1] = gy * invH;
    b[2] = (gx + gw) * invW;
    b[3] = (gy + gh) * invH;

    float v[4];
#pragma unroll
    for (int i = 0; i < 4; ++i) {
        int k = (int)k0 + i;
        int rr = (int)r;
        if (k >= 85) { k -= 85; ++rr; }   // wrap lands in cls of next row; rr < R
        v[i] = (k < 81) ? __ldg(&cls[(size_t)rr * 81 + k]) : b[k - 81];
    }
    float4 o; o.x = v[0]; o.y = v[1]; o.z = v[2]; o.w = v[3];
    plane[t] = o;
}

// ---------------- Proven R9 pair as fallback for odd shapes ----------------
__global__ void __launch_bounds__(256)
cls_broadcast_kernel(const float4* __restrict__ cls4, float4* __restrict__ out4,
                     int perC4, int rowlen, int maxClsIdx)
{
    int t = blockIdx.x * 256 + threadIdx.x;
    if (t >= perC4) return;
    const int c = blockIdx.y;
    unsigned rem0 = (unsigned)t << 2;
    unsigned r  = rem0 / (unsigned)rowlen;
    unsigned k0 = rem0 - r * (unsigned)rowlen;
    unsigned rr = r + (k0 >= (unsigned)(rowlen - 3));
    int idx = t - (int)rr;
    idx = min(idx, maxClsIdx);
    out4[(size_t)c * (size_t)perC4 + (size_t)t] = __ldg(&cls4[idx]);
}

__global__ void __launch_bounds__(256)
box_kernel_v2(const float4* __restrict__ regr4, const float4* __restrict__ rois,
              float* __restrict__ out, int R, int Cm1, int NC,
              float invW, float invH)
{
    int u = blockIdx.x * 256 + threadIdx.x;
    if (u >= 4 * R) return;
    const int c = blockIdx.y;
    const int r = u >> 2;
    const int j = u & 3;
    float4 roi = __ldg(&rois[r]);
    float4 tg  = __ldg(&regr4[(size_t)r * Cm1 + c]);
    const bool odd = (j & 1);
    const bool hi  = (j >= 2);
    float s   = odd ? roi.w : roi.z;
    float o   = odd ? roi.y : roi.x;
    float inv = odd ? invH  : invW;
    float t1  = odd ? tg.y  : tg.x;
    float t2  = odd ? tg.w  : tg.z;
    float base  = rintf(fmaf(s, t1, o));
    float extra = rintf(s * expf(t2));
    float val   = (base + (hi ? extra : 0.0f)) * inv;
    out[((size_t)c * R + r) * (size_t)(NC + 4) + NC + j] = val;
}

__global__ void __launch_bounds__(256)
bb_generic_kernel(const float* __restrict__ regr, const float* __restrict__ cls,
                  const float4* __restrict__ rois, float* __restrict__ out,
                  int R, int Cm1, int NC, float invW, float invH, long long total)
{
    long long idx = (long long)blockIdx.x * blockDim.x + threadIdx.x;
    long long stride = (long long)gridDim.x * blockDim.x;
    const int rowlen = NC + 4;
    const long long perC = (long long)R * rowlen;
    for (; idx < total; idx += stride) {
        int c   = (int)(idx / perC);
        int rem = (int)(idx - (long long)c * perC);
        int r   = rem / rowlen;
        int k   = rem - r * rowlen;
        float val;
        if (k < NC) {
            val = cls[(long long)r * NC + k];
        } else {
            float4 roi = __ldg(&rois[r]);
            const float* rg = regr + ((long long)r * Cm1 + c) * 4;
            int comp = k - NC;
            if (comp == 0)      val = rintf(fmaf(roi.z, rg[0], roi.x)) * invW;
            else if (comp == 1) val = rintf(fmaf(roi.w, rg[1], roi.y)) * invH;
            else if (comp == 2) val = (rintf(fmaf(roi.z, rg[0], roi.x)) +
                                       rintf(roi.z * expf(rg[2]))) * invW;
            else                val = (rintf(fmaf(roi.w, rg[1], roi.y)) +
                                       rintf(roi.w * expf(rg[3]))) * invH;
        }
        out[idx] = val;
    }
}

extern "C" void kernel_launch(void* const* d_in, const int* in_sizes, int n_in,
                              void* d_out, int out_size)
{
    const float*  regr = (const float*)d_in[0];   // [1, R, 4*Cm1]
    const float*  cls  = (const float*)d_in[1];   // [1, R, NC]
    const float4* rois = (const float4*)d_in[2];  // [1, R, 4]

    const int R   = in_sizes[2] / 4;
    const int Cm1 = in_sizes[0] / (R * 4);
    const int NC  = in_sizes[1] / R;
    const int rowlen = NC + 4;

    long long hw = (long long)in_sizes[3] / 3;    // H = W = isqrt(b_elems/3)
    int side = 1;
    while ((long long)(side + 1) * (side + 1) <= hw) ++side;
    const float invW = 1.0f / (float)side;
    const float invH = 1.0f / (float)side;

    float* out = (float*)d_out;
    const long long perC  = (long long)R * rowlen;
    const long long total = (long long)out_size;

    if (rowlen == 85 && (R % 4) == 0 &&
        total == (long long)Cm1 * perC && (perC % 4) == 0) {
        // One-pass specialized kernel
        const int perC4     = (int)(perC >> 2);
        const int groups    = R / 4;
        const int fastCount = 78 * groups;
        const int slowCount = 7 * groups;
        const int fastBlocks = (fastCount + 255) / 256;
        const int slowBlocks = (slowCount + 255) / 256;
        dim3 grid(fastBlocks + slowBlocks, Cm1);
        bb_onepass_kernel<<<grid, 256>>>(
            cls, (const float4*)cls, (const float4*)regr, rois,
            (float4*)out, perC4, R, Cm1,
            fastBlocks, fastCount, slowCount, invW, invH);
    } else if ((perC % 4) == 0 && (((long long)R * NC) % 4) == 0 &&
               total == (long long)Cm1 * perC) {
        // Proven two-pass path
        const int perC4 = (int)(perC >> 2);
        const int maxClsIdx = (int)(((long long)R * NC - 4) >> 2);
        dim3 gridA((perC4 + 255) / 256, Cm1);
        cls_broadcast_kernel<<<gridA, 256>>>(
            (const float4*)cls, (float4*)out, perC4, rowlen, maxClsIdx);
        dim3 gridB((4 * R + 255) / 256, Cm1);
        box_kernel_v2<<<gridB, 256>>>(
            (const float4*)regr, rois, out, R, Cm1, NC, invW, invH);
    } else {
        long long blocks = (total + 255) / 256;
        if (blocks > 262144) blocks = 262144;
        bb_generic_kernel<<<(unsigned)blocks, 256>>>(
            regr, cls, rois, out, R, Cm1, NC, invW, invH, total);
    }
}